// round 2
// baseline (speedup 1.0000x reference)
#include <cuda_runtime.h>

#define BB 256
#define TT 1024
#define DD 128
#define LL 16
#define OO 256

// Recurrence kernel tiling: per-thread R column split between registers and smem
#define KREG 176                 // rows of R held in registers (as 88 packed f32x2)
#define KSM  80                  // rows of R held in shared memory
#define RPAD 42                  // u64 slots per padded Rsm row (40 data + 2 pad -> conflict-free LDS.128)

#define SMEM2_BYTES (4096 + OO * RPAD * 8)   // s double-buffers (4KB) + Rsm (84KB) = 90112 B

// Scratch for the state-independent aggregation (256 MB) — static device array per harness rules.
__device__ float g_agg[(size_t)BB * TT * OO];

// ---------------------------------------------------------------------------
// Kernel 1: agg[b,t,o] = sum_l act_l( x[b,t,:]·sub_W[l,:] + sub_b[l] ) * agg_W[l,o]
// One 256-thread block handles 16 (b,t) rows.
// ---------------------------------------------------------------------------
__global__ void __launch_bounds__(256) act_agg_kernel(
    const float* __restrict__ x, const float* __restrict__ subW,
    const float* __restrict__ subb, const float* __restrict__ aggW)
{
    __shared__ float xs[16][DD];          // 16 input rows
    __shared__ float ws[LL][DD + 4];      // sub_W rows, padded for conflict-free float4 LDS
    __shared__ float as_[16][LL + 1];     // activations, padded

    const int tid = threadIdx.x;
    const size_t row0 = (size_t)blockIdx.x * 16;   // global (b*T + t) row

    // stage sub_W
    for (int i = tid; i < LL * DD; i += 256) ws[i / DD][i % DD] = subW[i];
    // stage 16 x-rows (float4, coalesced)
    {
        const float4* xg = (const float4*)(x + row0 * DD);
        float4* xs4 = (float4*)&xs[0][0];
        for (int i = tid; i < 16 * DD / 4; i += 256) xs4[i] = xg[i];
    }
    __syncthreads();

    // pre + activation: thread (r, l), 16x16 = 256 threads
    {
        const int l = tid & 15, r = tid >> 4;
        const float4* xr = (const float4*)&xs[r][0];
        const float4* wr = (const float4*)&ws[l][0];
        float acc = 0.f;
#pragma unroll
        for (int i = 0; i < DD / 4; i++) {
            float4 a = xr[i], b = wr[i];
            acc += a.x * b.x; acc += a.y * b.y; acc += a.z * b.z; acc += a.w * b.w;
        }
        acc += subb[l];
        float v;
        const int m = l & 3;
        if (m == 0)      v = tanhf(acc);
        else if (m == 1) v = fmaxf(acc, 0.f);
        else if (m == 2) v = 1.f / (1.f + expf(-acc));
        else             v = acc;
        as_[r][l] = v;
    }
    __syncthreads();

    // aggregation: thread o = tid, agg_W column in registers
    {
        const int o = tid;
        float wcol[LL];
#pragma unroll
        for (int l = 0; l < LL; l++) wcol[l] = aggW[l * OO + o];
        float* outp = g_agg + row0 * OO + o;
#pragma unroll
        for (int r = 0; r < 16; r++) {
            float acc = 0.f;
#pragma unroll
            for (int l = 0; l < LL; l++) acc += as_[r][l] * wcol[l];
            outp[(size_t)r * OO] = acc;
        }
    }
}

// ---------------------------------------------------------------------------
// Kernel 2: the recurrence  s_t = agg_t + s_{t-1} @ R,   out[b,t,:] = s_t
// 128 CTAs (one per batch pair), 256 threads (thread = output column o).
// R column per thread: 176 rows in registers (88 packed f32x2), 80 rows in smem.
// All MACs via packed fma.rn.f32x2 (2 MACs/instr).
// ---------------------------------------------------------------------------
#define FMA2(acc, a, b) asm("fma.rn.f32x2 %0, %1, %2, %0;" : "+l"(acc) : "l"(a), "l"(b))

__global__ void __launch_bounds__(256, 1) recur_kernel(
    const float* __restrict__ R, float* __restrict__ out)
{
    extern __shared__ unsigned char dyn[];
    float* sbuf = (float*)dyn;                                   // [2 bufs][2 batches][256]
    unsigned long long* Rsm = (unsigned long long*)(dyn + 4096); // [256 cols][RPAD]

    const int o = threadIdx.x;
    const int b0 = blockIdx.x * 2;

    // Load R column for output o: k in [0,KREG) into registers as packed pairs
    unsigned long long Rp[KREG / 2];
#pragma unroll
    for (int i = 0; i < KREG / 2; i++) {
        float lo = R[(2 * i) * OO + o];
        float hi = R[(2 * i + 1) * OO + o];
        asm("mov.b64 %0, {%1, %2};" : "=l"(Rp[i]) : "f"(lo), "f"(hi));
    }
    // k in [KREG, 256) into shared memory (per-thread row, padded)
#pragma unroll
    for (int i = 0; i < KSM / 2; i++) {
        float lo = R[(KREG + 2 * i) * OO + o];
        float hi = R[(KREG + 2 * i + 1) * OO + o];
        unsigned long long p;
        asm("mov.b64 %0, {%1, %2};" : "=l"(p) : "f"(lo), "f"(hi));
        Rsm[(size_t)o * RPAD + i] = p;
    }
    // init state = 0 in buffer 0 (both batches)
    sbuf[o] = 0.f;
    sbuf[256 + o] = 0.f;
    __syncthreads();

    const float* ag0 = g_agg + (size_t)b0 * TT * OO + o;
    const float* ag1 = ag0 + (size_t)TT * OO;
    float* o0 = out + (size_t)b0 * TT * OO + o;
    float* o1 = o0 + (size_t)TT * OO;

    float a0 = ag0[0];
    float a1 = ag1[0];
    const ulonglong2* Ro2 = (const ulonglong2*)(Rsm + (size_t)o * RPAD);

    for (int t = 0; t < TT; t++) {
        const int buf = t & 1;
        // prefetch next timestep's agg (hidden under the FMA chain)
        const int tn = (t + 1 < TT) ? (t + 1) : t;
        const float an0 = ag0[tn * OO];
        const float an1 = ag1[tn * OO];

        const ulonglong2* sA2 = (const ulonglong2*)(sbuf + buf * 512);
        const ulonglong2* sB2 = (const ulonglong2*)(sbuf + buf * 512 + 256);

        unsigned long long accA0 = 0ULL, accA1 = 0ULL;
        unsigned long long accB0 = 0ULL, accB1 = 0ULL;

        // registers part: k in [0, KREG)
#pragma unroll
        for (int j = 0; j < KREG / 4; j++) {          // 44 chunks of 4 k's
            ulonglong2 vA = sA2[j];
            ulonglong2 vB = sB2[j];
            FMA2(accA0, vA.x, Rp[2 * j]);
            FMA2(accA1, vA.y, Rp[2 * j + 1]);
            FMA2(accB0, vB.x, Rp[2 * j]);
            FMA2(accB1, vB.y, Rp[2 * j + 1]);
        }
        // smem part: k in [KREG, 256) — R value loaded once, reused for both batches
#pragma unroll
        for (int j = 0; j < KSM / 4; j++) {           // 20 chunks
            ulonglong2 rv = Ro2[j];
            ulonglong2 vA = sA2[KREG / 4 + j];
            ulonglong2 vB = sB2[KREG / 4 + j];
            FMA2(accA0, vA.x, rv.x);
            FMA2(accA1, vA.y, rv.y);
            FMA2(accB0, vB.x, rv.x);
            FMA2(accB1, vB.y, rv.y);
        }

        float xA0, yA0, xA1, yA1, xB0, yB0, xB1, yB1;
        asm("mov.b64 {%0, %1}, %2;" : "=f"(xA0), "=f"(yA0) : "l"(accA0));
        asm("mov.b64 {%0, %1}, %2;" : "=f"(xA1), "=f"(yA1) : "l"(accA1));
        asm("mov.b64 {%0, %1}, %2;" : "=f"(xB0), "=f"(yB0) : "l"(accB0));
        asm("mov.b64 {%0, %1}, %2;" : "=f"(xB1), "=f"(yB1) : "l"(accB1));

        const float nsA = a0 + ((xA0 + yA0) + (xA1 + yA1));
        const float nsB = a1 + ((xB0 + yB0) + (xB1 + yB1));

        // publish new state to the other buffer, stream result to gmem
        sbuf[(buf ^ 1) * 512 + o] = nsA;
        sbuf[(buf ^ 1) * 512 + 256 + o] = nsB;
        o0[(size_t)t * OO] = nsA;
        o1[(size_t)t * OO] = nsB;

        a0 = an0; a1 = an1;
        __syncthreads();   // separates this step's reads from next step's writes
    }
}

// ---------------------------------------------------------------------------
extern "C" void kernel_launch(void* const* d_in, const int* in_sizes, int n_in,
                              void* d_out, int out_size)
{
    const float* x    = (const float*)d_in[0];
    const float* subW = (const float*)d_in[1];
    const float* subb = (const float*)d_in[2];
    const float* aggW = (const float*)d_in[3];
    const float* R    = (const float*)d_in[4];
    float* out = (float*)d_out;

    cudaFuncSetAttribute(recur_kernel, cudaFuncAttributeMaxDynamicSharedMemorySize,
                         SMEM2_BYTES);

    act_agg_kernel<<<(BB * TT) / 16, 256>>>(x, subW, subb, aggW);
    recur_kernel<<<BB / 2, 256, SMEM2_BYTES>>>(R, out);
}

// round 3
// speedup vs baseline: 1.0002x; 1.0002x over previous
#include <cuda_runtime.h>

#define BB 256
#define TT 1024
#define DD 128
#define LL 16
#define OO 256

// Recurrence kernel tiling: per-thread R column split between registers and smem
#define KREG 176                 // rows of R held in registers (as 88 packed f32x2)
#define KSM  80                  // rows of R held in shared memory
#define RPAD 42                  // u64 slots per padded Rsm row (40 data + 2 pad -> conflict-free LDS.128)

#define SMEM2_BYTES (4096 + OO * RPAD * 8)   // s double-buffers (4KB) + Rsm (84KB) = 90112 B

// Scratch for the state-independent aggregation (256 MB) — static device array per harness rules.
__device__ float g_agg[(size_t)BB * TT * OO];

// ---------------------------------------------------------------------------
// Kernel 1: agg[b,t,o] = sum_l act_l( x[b,t,:]·sub_W[l,:] + sub_b[l] ) * agg_W[l,o]
// One 256-thread block handles 16 (b,t) rows.
// ---------------------------------------------------------------------------
__global__ void __launch_bounds__(256) act_agg_kernel(
    const float* __restrict__ x, const float* __restrict__ subW,
    const float* __restrict__ subb, const float* __restrict__ aggW)
{
    __shared__ float xs[16][DD];          // 16 input rows
    __shared__ float ws[LL][DD + 4];      // sub_W rows, padded for conflict-free float4 LDS
    __shared__ float as_[16][LL + 1];     // activations, padded

    const int tid = threadIdx.x;
    const size_t row0 = (size_t)blockIdx.x * 16;   // global (b*T + t) row

    // stage sub_W
    for (int i = tid; i < LL * DD; i += 256) ws[i / DD][i % DD] = subW[i];
    // stage 16 x-rows (float4, coalesced)
    {
        const float4* xg = (const float4*)(x + row0 * DD);
        float4* xs4 = (float4*)&xs[0][0];
        for (int i = tid; i < 16 * DD / 4; i += 256) xs4[i] = xg[i];
    }
    __syncthreads();

    // pre + activation: thread (r, l), 16x16 = 256 threads
    {
        const int l = tid & 15, r = tid >> 4;
        const float4* xr = (const float4*)&xs[r][0];
        const float4* wr = (const float4*)&ws[l][0];
        float acc = 0.f;
#pragma unroll
        for (int i = 0; i < DD / 4; i++) {
            float4 a = xr[i], b = wr[i];
            acc += a.x * b.x; acc += a.y * b.y; acc += a.z * b.z; acc += a.w * b.w;
        }
        acc += subb[l];
        float v;
        const int m = l & 3;
        if (m == 0)      v = tanhf(acc);
        else if (m == 1) v = fmaxf(acc, 0.f);
        else if (m == 2) v = 1.f / (1.f + expf(-acc));
        else             v = acc;
        as_[r][l] = v;
    }
    __syncthreads();

    // aggregation: thread o = tid, agg_W column in registers
    {
        const int o = tid;
        float wcol[LL];
#pragma unroll
        for (int l = 0; l < LL; l++) wcol[l] = aggW[l * OO + o];
        float* outp = g_agg + row0 * OO + o;
#pragma unroll
        for (int r = 0; r < 16; r++) {
            float acc = 0.f;
#pragma unroll
            for (int l = 0; l < LL; l++) acc += as_[r][l] * wcol[l];
            outp[(size_t)r * OO] = acc;
        }
    }
}

// ---------------------------------------------------------------------------
// Kernel 2: the recurrence  s_t = agg_t + s_{t-1} @ R,   out[b,t,:] = s_t
// 128 CTAs (one per batch pair), 256 threads (thread = output column o).
// R column per thread: 176 rows in registers (88 packed f32x2), 80 rows in smem.
// All MACs via packed fma.rn.f32x2 (2 MACs/instr).
// ---------------------------------------------------------------------------
#define FMA2(acc, a, b) asm("fma.rn.f32x2 %0, %1, %2, %0;" : "+l"(acc) : "l"(a), "l"(b))

__global__ void __launch_bounds__(256, 1) recur_kernel(
    const float* __restrict__ R, float* __restrict__ out)
{
    extern __shared__ unsigned char dyn[];
    float* sbuf = (float*)dyn;                                   // [2 bufs][2 batches][256]
    unsigned long long* Rsm = (unsigned long long*)(dyn + 4096); // [256 cols][RPAD]

    const int o = threadIdx.x;
    const int b0 = blockIdx.x * 2;

    // Load R column for output o: k in [0,KREG) into registers as packed pairs
    unsigned long long Rp[KREG / 2];
#pragma unroll
    for (int i = 0; i < KREG / 2; i++) {
        float lo = R[(2 * i) * OO + o];
        float hi = R[(2 * i + 1) * OO + o];
        asm("mov.b64 %0, {%1, %2};" : "=l"(Rp[i]) : "f"(lo), "f"(hi));
    }
    // k in [KREG, 256) into shared memory (per-thread row, padded)
#pragma unroll
    for (int i = 0; i < KSM / 2; i++) {
        float lo = R[(KREG + 2 * i) * OO + o];
        float hi = R[(KREG + 2 * i + 1) * OO + o];
        unsigned long long p;
        asm("mov.b64 %0, {%1, %2};" : "=l"(p) : "f"(lo), "f"(hi));
        Rsm[(size_t)o * RPAD + i] = p;
    }
    // init state = 0 in buffer 0 (both batches)
    sbuf[o] = 0.f;
    sbuf[256 + o] = 0.f;
    __syncthreads();

    const float* ag0 = g_agg + (size_t)b0 * TT * OO + o;
    const float* ag1 = ag0 + (size_t)TT * OO;
    float* o0 = out + (size_t)b0 * TT * OO + o;
    float* o1 = o0 + (size_t)TT * OO;

    float a0 = ag0[0];
    float a1 = ag1[0];
    const ulonglong2* Ro2 = (const ulonglong2*)(Rsm + (size_t)o * RPAD);

    for (int t = 0; t < TT; t++) {
        const int buf = t & 1;
        // prefetch next timestep's agg (hidden under the FMA chain)
        const int tn = (t + 1 < TT) ? (t + 1) : t;
        const float an0 = ag0[tn * OO];
        const float an1 = ag1[tn * OO];

        const ulonglong2* sA2 = (const ulonglong2*)(sbuf + buf * 512);
        const ulonglong2* sB2 = (const ulonglong2*)(sbuf + buf * 512 + 256);

        unsigned long long accA0 = 0ULL, accA1 = 0ULL;
        unsigned long long accB0 = 0ULL, accB1 = 0ULL;

        // registers part: k in [0, KREG)
#pragma unroll
        for (int j = 0; j < KREG / 4; j++) {          // 44 chunks of 4 k's
            ulonglong2 vA = sA2[j];
            ulonglong2 vB = sB2[j];
            FMA2(accA0, vA.x, Rp[2 * j]);
            FMA2(accA1, vA.y, Rp[2 * j + 1]);
            FMA2(accB0, vB.x, Rp[2 * j]);
            FMA2(accB1, vB.y, Rp[2 * j + 1]);
        }
        // smem part: k in [KREG, 256) — R value loaded once, reused for both batches
#pragma unroll
        for (int j = 0; j < KSM / 4; j++) {           // 20 chunks
            ulonglong2 rv = Ro2[j];
            ulonglong2 vA = sA2[KREG / 4 + j];
            ulonglong2 vB = sB2[KREG / 4 + j];
            FMA2(accA0, vA.x, rv.x);
            FMA2(accA1, vA.y, rv.y);
            FMA2(accB0, vB.x, rv.x);
            FMA2(accB1, vB.y, rv.y);
        }

        float xA0, yA0, xA1, yA1, xB0, yB0, xB1, yB1;
        asm("mov.b64 {%0, %1}, %2;" : "=f"(xA0), "=f"(yA0) : "l"(accA0));
        asm("mov.b64 {%0, %1}, %2;" : "=f"(xA1), "=f"(yA1) : "l"(accA1));
        asm("mov.b64 {%0, %1}, %2;" : "=f"(xB0), "=f"(yB0) : "l"(accB0));
        asm("mov.b64 {%0, %1}, %2;" : "=f"(xB1), "=f"(yB1) : "l"(accB1));

        const float nsA = a0 + ((xA0 + yA0) + (xA1 + yA1));
        const float nsB = a1 + ((xB0 + yB0) + (xB1 + yB1));

        // publish new state to the other buffer, stream result to gmem
        sbuf[(buf ^ 1) * 512 + o] = nsA;
        sbuf[(buf ^ 1) * 512 + 256 + o] = nsB;
        o0[(size_t)t * OO] = nsA;
        o1[(size_t)t * OO] = nsB;

        a0 = an0; a1 = an1;
        __syncthreads();   // separates this step's reads from next step's writes
    }
}

// ---------------------------------------------------------------------------
extern "C" void kernel_launch(void* const* d_in, const int* in_sizes, int n_in,
                              void* d_out, int out_size)
{
    const float* x    = (const float*)d_in[0];
    const float* subW = (const float*)d_in[1];
    const float* subb = (const float*)d_in[2];
    const float* aggW = (const float*)d_in[3];
    const float* R    = (const float*)d_in[4];
    float* out = (float*)d_out;

    cudaFuncSetAttribute(recur_kernel, cudaFuncAttributeMaxDynamicSharedMemorySize,
                         SMEM2_BYTES);

    act_agg_kernel<<<(BB * TT) / 16, 256>>>(x, subW, subb, aggW);
    recur_kernel<<<BB / 2, 256, SMEM2_BYTES>>>(R, out);
}